// round 5
// baseline (speedup 1.0000x reference)
#include <cuda_runtime.h>
#include <cuda_bf16.h>

#define S_DIM 128
#define A_DIM 96
#define B_DIM 256
#define LX    512
#define LY    256

// C'[s][a] = -softmax(P, axis=1)[s][a]   (cost - 1 = C')
__device__ float g_Cn[S_DIM * A_DIM];

__global__ void softmax_neg_kernel(const float* __restrict__ P) {
    int row  = blockIdx.x;
    int lane = threadIdx.x;
    const float* pr = P + row * A_DIM;
    float v0 = pr[lane], v1 = pr[lane + 32], v2 = pr[lane + 64];
    float m = fmaxf(v0, fmaxf(v1, v2));
    #pragma unroll
    for (int o = 16; o > 0; o >>= 1) m = fmaxf(m, __shfl_xor_sync(0xffffffffu, m, o));
    float e0 = expf(v0 - m), e1 = expf(v1 - m), e2 = expf(v2 - m);
    float s = e0 + e1 + e2;
    #pragma unroll
    for (int o = 16; o > 0; o >>= 1) s += __shfl_xor_sync(0xffffffffu, s, o);
    float inv = -1.0f / s;
    g_Cn[row * A_DIM + lane     ] = e0 * inv;
    g_Cn[row * A_DIM + lane + 32] = e1 * inv;
    g_Cn[row * A_DIM + lane + 64] = e2 * inv;
}

// One warp per batch; lane-skewed wavefront processing TWO DP rows per step.
// Lane L owns columns j = 8L+1..8L+8 (D' = D - j space). At step s it does
// rows rA = 2s-1-2L and rB = 2s-2L. Lane L-1's step (s-1) produced exactly
// the boundary column 8L for rows rA and rB -> one 2-value shfl per step.
//   E'[j]   = min(D'_{r-1}[j]+1, D'_{r-1}[j-1]+c')
//   D'_r[j] = min(prefixmin(E')[j], D'_r[8L])          (boundary via shfl / analytic)

#define CLX(i) min(max((i), 0), xcap)

#define DP_STEP(sv, COMMIT)  do {                                              \
    /* gather costs for step (sv)+2 using xs values loaded earlier */          \
    float gA_[8], gB_[8];                                                      \
    {                                                                          \
        const float* pA_ = g_Cn + xpA * A_DIM;                                 \
        const float* pB_ = g_Cn + xpB * A_DIM;                                 \
        _Pragma("unroll")                                                      \
        for (int k = 0; k < 8; ++k) { gA_[k] = pA_[y[k]]; gB_[k] = pB_[y[k]]; }\
    }                                                                          \
    /* xs feeding step (sv)+3 gathers */                                       \
    int xnA_ = xsb[CLX(2*(sv) + 4 - L2)];                                      \
    int xnB_ = xsb[CLX(2*(sv) + 5 - L2)];                                      \
    float bAe_ = is0 ? rfA          : bA;                                      \
    float bBe_ = is0 ? (rfA + 1.0f) : bB;                                      \
    float bp_  = is0 ? (rfA - 1.0f) : bprev;                                   \
    /* row A from D (= row rA-1) */                                            \
    float EA_[8];                                                              \
    EA_[0] = fminf(D[0] + 1.0f, bp_ + c0A[0]);                                 \
    _Pragma("unroll")                                                          \
    for (int k = 1; k < 8; ++k) EA_[k] = fminf(D[k] + 1.0f, D[k-1] + c0A[k]);  \
    float PA_[8]; PA_[0] = EA_[0];                                             \
    _Pragma("unroll")                                                          \
    for (int k = 1; k < 8; ++k) PA_[k] = fminf(PA_[k-1], EA_[k]);              \
    _Pragma("unroll")                                                          \
    for (int k = 0; k < 8; ++k) DA[k] = fminf(PA_[k], bAe_);                   \
    /* row B from DA (= row rA) */                                             \
    float EB_[8];                                                              \
    EB_[0] = fminf(DA[0] + 1.0f, bAe_ + c0B[0]);                               \
    _Pragma("unroll")                                                          \
    for (int k = 1; k < 8; ++k) EB_[k] = fminf(DA[k] + 1.0f, DA[k-1] + c0B[k]);\
    float PB_[8]; PB_[0] = EB_[0];                                             \
    _Pragma("unroll")                                                          \
    for (int k = 1; k < 8; ++k) PB_[k] = fminf(PB_[k-1], EB_[k]);              \
    if (COMMIT) {                                                              \
        _Pragma("unroll")                                                      \
        for (int k = 0; k < 8; ++k) D[k] = fminf(PB_[k], bBe_);                \
    }                                                                          \
    float sA_ = __shfl_up_sync(0xffffffffu, DA[7], 1);                         \
    float sB_ = __shfl_up_sync(0xffffffffu, D[7], 1);                          \
    bprev = bB;  bA = sA_;  bB = sB_;                                          \
    rfA += 2.0f;                                                               \
    _Pragma("unroll")                                                          \
    for (int k = 0; k < 8; ++k) {                                              \
        c0A[k] = c1A[k];  c0B[k] = c1B[k];                                     \
        c1A[k] = gA_[k];  c1B[k] = gB_[k];                                     \
    }                                                                          \
    xpA = xnA_;  xpB = xnB_;                                                   \
} while (0)

__global__ void __launch_bounds__(32, 4) dp_kernel(
    const int* __restrict__ xs,
    const int* __restrict__ ys,
    const int* __restrict__ xlen,
    const int* __restrict__ ylen,
    float* __restrict__ out)
{
    const int b    = blockIdx.x;
    const int lane = threadIdx.x;
    const int xl   = xlen[b] - 1;     // target row (1..511)
    const int yl   = ylen[b] - 1;     // target col (1..255)

    const int* xsb = xs + (size_t)b * LX;
    const int* ysb = ys + (size_t)b * LY;

    int y[8];
    #pragma unroll
    for (int k = 0; k < 8; ++k) y[k] = ysb[lane * 8 + k];

    float D[8], DA[8];
    #pragma unroll
    for (int k = 0; k < 8; ++k) { D[k] = 0.0f; DA[k] = 0.0f; }

    const int t_lane = (yl - 1) >> 3;
    const int k_t    = (yl - 1) & 7;
    const int S      = t_lane + ((xl + 1) >> 1);  // lane t_lane reaches row xl
    const int xcap   = xl - 1;
    const int L2     = 2 * lane;
    const bool is0   = (lane == 0);

    float bA = 0.0f, bB = 0.0f, bprev = 0.0f;
    float rfA = (float)(1 - L2);      // rA at step 1

    // prefill: costs for steps 1,2; xs values feeding step-3 gathers
    float c0A[8], c0B[8], c1A[8], c1B[8];
    {
        const float* p1A = g_Cn + xsb[CLX(0 - L2)] * A_DIM;
        const float* p1B = g_Cn + xsb[CLX(1 - L2)] * A_DIM;
        const float* p2A = g_Cn + xsb[CLX(2 - L2)] * A_DIM;
        const float* p2B = g_Cn + xsb[CLX(3 - L2)] * A_DIM;
        #pragma unroll
        for (int k = 0; k < 8; ++k) {
            c0A[k] = p1A[y[k]];  c0B[k] = p1B[y[k]];
            c1A[k] = p2A[y[k]];  c1B[k] = p2B[y[k]];
        }
    }
    int xpA = xsb[CLX(4 - L2)];
    int xpB = xsb[CLX(5 - L2)];

    // ramp-in (freeze predicate live), then steady state (no predicate)
    int s = 1;
    const int rampEnd = min(31, S);
    for (; s <= rampEnd; ++s) {
        const bool act = (s > lane);
        DP_STEP(s, act);
    }
    #pragma unroll 2
    for (; s <= S; ++s) {
        DP_STEP(s, true);
    }

    // xl odd  -> row xl was the A-row of step S (in DA)
    // xl even -> row xl was the B-row of step S (in D)
    if (lane == t_lane) {
        float res = (xl & 1) ? DA[k_t] : D[k_t];
        out[b] = res + (float)yl;
    }
}

extern "C" void kernel_launch(void* const* d_in, const int* in_sizes, int n_in,
                              void* d_out, int out_size) {
    const float* P    = (const float*)d_in[0];
    const int*   xs   = (const int*)d_in[1];
    const int*   ys   = (const int*)d_in[2];
    const int*   xlen = (const int*)d_in[3];
    const int*   ylen = (const int*)d_in[4];
    float*       out  = (float*)d_out;

    softmax_neg_kernel<<<S_DIM, 32>>>(P);
    dp_kernel<<<B_DIM, 32>>>(xs, ys, xlen, ylen, out);
}

// round 6
// speedup vs baseline: 1.1066x; 1.1066x over previous
#include <cuda_runtime.h>
#include <cuda_bf16.h>

#define S_DIM 128
#define A_DIM 96
#define B_DIM 256
#define LX    512
#define LY    256

// C'[s][a] = -softmax(P, axis=1)[s][a]   (cost - 1 = C')
__device__ float g_Cn[S_DIM * A_DIM];

__global__ void softmax_neg_kernel(const float* __restrict__ P) {
    int row  = blockIdx.x;
    int lane = threadIdx.x;
    const float* pr = P + row * A_DIM;
    float v0 = pr[lane], v1 = pr[lane + 32], v2 = pr[lane + 64];
    float m = fmaxf(v0, fmaxf(v1, v2));
    #pragma unroll
    for (int o = 16; o > 0; o >>= 1) m = fmaxf(m, __shfl_xor_sync(0xffffffffu, m, o));
    float e0 = expf(v0 - m), e1 = expf(v1 - m), e2 = expf(v2 - m);
    float s = e0 + e1 + e2;
    #pragma unroll
    for (int o = 16; o > 0; o >>= 1) s += __shfl_xor_sync(0xffffffffu, s, o);
    float inv = -1.0f / s;
    g_Cn[row * A_DIM + lane     ] = e0 * inv;
    g_Cn[row * A_DIM + lane + 32] = e1 * inv;
    g_Cn[row * A_DIM + lane + 64] = e2 * inv;
}

// One warp per batch, lane-skewed wavefront (R4 structure), with the cost
// table staged in shared memory so the divergent per-step gathers are LDS
// instead of replay-heavy divergent LDG.
__global__ void __launch_bounds__(32, 4) dp_kernel(
    const int* __restrict__ xs,
    const int* __restrict__ ys,
    const int* __restrict__ xlen,
    const int* __restrict__ ylen,
    float* __restrict__ out)
{
    __shared__ float sC[S_DIM * A_DIM];   // 48 KB, exactly the static limit

    const int b    = blockIdx.x;
    const int lane = threadIdx.x;

    // stage cost table: 12288 floats = 3072 float4, coalesced
    {
        const float4* src = (const float4*)g_Cn;
        float4*       dst = (float4*)sC;
        #pragma unroll 4
        for (int i = lane; i < (S_DIM * A_DIM) / 4; i += 32) dst[i] = src[i];
        __syncthreads();
    }

    const int xl = xlen[b] - 1;   // target row (1..LX-1)
    const int yl = ylen[b] - 1;   // target col (1..LY-1)

    const int* xsb = xs + (size_t)b * LX;
    const int* ysb = ys + (size_t)b * LY;

    int y[8];
    #pragma unroll
    for (int k = 0; k < 8; ++k) y[k] = ysb[lane * 8 + k];

    float D[8];
    #pragma unroll
    for (int k = 0; k < 8; ++k) D[k] = 0.0f;   // row 0: D'[j] = 0

    const int t_lane = (yl - 1) >> 3;
    const int k_t    = (yl - 1) & 7;
    const int s_end  = xl + t_lane;     // lane t_lane reaches row xl here
    const int xcap   = xl - 1;          // clamp bound for xs index

    float Dl    = 0.0f;                 // shfl'd boundary for upcoming step
    float bprev = 0.0f;                 // D'_{r-1}[jb-1]
    float rf    = (float)(1 - lane);    // float(r) for lane-0 boundary
    const bool is0 = (lane == 0);

    const int r1 = 1 - lane;            // row at step 1

    // cost pipeline: cb[p] = gathered costs for row (r + p); row q uses xs[q-1]
    float cb[4][8];
    #pragma unroll
    for (int p = 0; p < 4; ++p) {
        int q  = r1 + p - 1;
        int xv = xsb[min(max(q, 0), xcap)];
        const float* rowp = sC + xv * A_DIM;
        #pragma unroll
        for (int k = 0; k < 8; ++k) cb[p][k] = rowp[y[k]];
    }
    // xs pipeline (depth 3): xsv[i] = xs[clamp(r1 + 3 + i)] feeds cost row r1+4+i
    int xsv[3];
    #pragma unroll
    for (int i = 0; i < 3; ++i) xsv[i] = xsb[min(max(r1 + 3 + i, 0), xcap)];

    #pragma unroll 4
    for (int s = 1; s <= s_end; ++s) {
        const int r = s - lane;

        // prefetch: cost for row r+4 (uses xs[r+3] = xsv[0]); refill xs pipe
        float cnew[8];
        {
            const float* rowp = sC + xsv[0] * A_DIM;
            #pragma unroll
            for (int k = 0; k < 8; ++k) cnew[k] = rowp[y[k]];
        }
        int xnew = xsb[min(max(r + 6, 0), xcap)];

        float Dl_eff = is0 ? rf : Dl;   // boundary D'_r[8L] (lane0: analytic r)

        // E and its in-lane inclusive prefix-min (log depth)
        float E[8];
        E[0] = fminf(D[0] + 1.0f, bprev + cb[0][0]);
        #pragma unroll
        for (int k = 1; k < 8; ++k)
            E[k] = fminf(D[k] + 1.0f, D[k - 1] + cb[0][k]);

        float t1[8];
        t1[0] = E[0];
        #pragma unroll
        for (int k = 1; k < 8; ++k) t1[k] = fminf(E[k], E[k - 1]);
        float t2[8];
        t2[0] = t1[0]; t2[1] = t1[1];
        #pragma unroll
        for (int k = 2; k < 8; ++k) t2[k] = fminf(t1[k], t1[k - 2]);
        float t3[8];
        #pragma unroll
        for (int k = 0; k < 4; ++k) t3[k] = t2[k];
        #pragma unroll
        for (int k = 4; k < 8; ++k) t3[k] = fminf(t2[k], t2[k - 4]);

        // freeze only during ramp-in (r < 1); ramp-out garbage is never consumed
        const bool act = (s > lane);
        #pragma unroll
        for (int k = 0; k < 8; ++k)
            D[k] = act ? fminf(t3[k], Dl_eff) : D[k];

        float sh = __shfl_up_sync(0xffffffffu, D[7], 1);
        bprev = Dl_eff;
        Dl    = sh;
        rf   += 1.0f;

        // rotate pipelines (register renames under unroll)
        #pragma unroll
        for (int k = 0; k < 8; ++k) {
            cb[0][k] = cb[1][k]; cb[1][k] = cb[2][k];
            cb[2][k] = cb[3][k]; cb[3][k] = cnew[k];
        }
        xsv[0] = xsv[1]; xsv[1] = xsv[2]; xsv[2] = xnew;
    }

    // lane t_lane's D holds row xl; convert back to D-space
    if (lane == t_lane) out[b] = D[k_t] + (float)yl;
}

extern "C" void kernel_launch(void* const* d_in, const int* in_sizes, int n_in,
                              void* d_out, int out_size) {
    const float* P    = (const float*)d_in[0];
    const int*   xs   = (const int*)d_in[1];
    const int*   ys   = (const int*)d_in[2];
    const int*   xlen = (const int*)d_in[3];
    const int*   ylen = (const int*)d_in[4];
    float*       out  = (float*)d_out;

    softmax_neg_kernel<<<S_DIM, 32>>>(P);
    dp_kernel<<<B_DIM, 32>>>(xs, ys, xlen, ylen, out);
}

// round 7
// speedup vs baseline: 1.2147x; 1.0977x over previous
#include <cuda_runtime.h>
#include <cuda_bf16.h>

#define S_DIM 128
#define A_DIM 96
#define B_DIM 256
#define LX    512
#define LY    256
#define XOFF_STRIDE 584   // padded clamped xs byte-offset table per batch

// g_Cn[s][a] = -softmax(P,axis=1)[s][a] - 1   (so cost-1 is baked in: c'' )
__device__ float g_Cn[S_DIM * A_DIM];
// Per-batch gathered cost table: Gt[b][x][j] = g_Cn[x][ys[b][j]]
__device__ float g_Gt[(size_t)B_DIM * S_DIM * LY];
// xoff[b][t] = clamp(t-32, 0, xl-1) -> xs[b][.] * 1024  (byte row offset in Gt)
__device__ int   g_xoff[B_DIM * XOFF_STRIDE];

__global__ void softmax_neg_kernel(const float* __restrict__ P) {
    int row  = blockIdx.x;
    int lane = threadIdx.x;
    const float* pr = P + row * A_DIM;
    float v0 = pr[lane], v1 = pr[lane + 32], v2 = pr[lane + 64];
    float m = fmaxf(v0, fmaxf(v1, v2));
    #pragma unroll
    for (int o = 16; o > 0; o >>= 1) m = fmaxf(m, __shfl_xor_sync(0xffffffffu, m, o));
    float e0 = expf(v0 - m), e1 = expf(v1 - m), e2 = expf(v2 - m);
    float s = e0 + e1 + e2;
    #pragma unroll
    for (int o = 16; o > 0; o >>= 1) s += __shfl_xor_sync(0xffffffffu, s, o);
    float inv = -1.0f / s;
    g_Cn[row * A_DIM + lane     ] = e0 * inv - 1.0f;
    g_Cn[row * A_DIM + lane + 32] = e1 * inv - 1.0f;
    g_Cn[row * A_DIM + lane + 64] = e2 * inv - 1.0f;
}

// One block per batch: build Gt[b] (gather through smem) and xoff[b].
__global__ void build_kernel(const int* __restrict__ xs,
                             const int* __restrict__ ys,
                             const int* __restrict__ xlen) {
    __shared__ float sC[S_DIM * A_DIM];
    const int b   = blockIdx.x;
    const int tid = threadIdx.x;

    {   // stage cost table (12288 floats = 3072 float4)
        const float4* src = (const float4*)g_Cn;
        float4*       dst = (float4*)sC;
        #pragma unroll
        for (int i = tid; i < (S_DIM * A_DIM) / 4; i += 256) dst[i] = src[i];
    }

    const int xl   = xlen[b] - 1;
    const int xcap = xl - 1;
    const int* xsb = xs + (size_t)b * LX;
    for (int t = tid; t < XOFF_STRIDE; t += 256) {
        int q = t - 32;
        int v = min(max(q, 0), xcap);
        g_xoff[b * XOFF_STRIDE + t] = xsb[v] * (LY * 4);
    }
    __syncthreads();

    const int yj = ys[(size_t)b * LY + tid];
    float* ob = g_Gt + (size_t)b * S_DIM * LY + tid;
    #pragma unroll 4
    for (int x = 0; x < S_DIM; ++x)
        ob[x * LY] = sC[x * A_DIM + yj];
}

// One warp per batch, lane-skewed wavefront, D'' = D - j - r space.
//   E''[j]    = min(D''_{r-1}[j], D''_{r-1}[j-1] + c'')      (c'' = -softmax - 1)
//   D''_r[j]  = min(prefixmin(E'')[j], D''_r[8L])            (lane-0 boundary = 0)
// Costs arrive as 2 x LDG.128 from the per-batch Gt table; row byte-offsets
// from xoff. Both behind depth-4 register pipelines. out = D'' + xl + yl.

#define DP_STEP(COMMIT) do {                                                   \
    /* prefetch costs for step s+4 (xo0 = xoff byte offset) */                 \
    const char* rp_ = Gtb + xo0;                                               \
    float4 nA_ = *(const float4*)rp_;                                          \
    float4 nB_ = *(const float4*)(rp_ + 16);                                   \
    int xnew_ = *xpr; ++xpr;       /* xoff for step s+8 */                     \
    float Dl_eff = is0 ? 0.0f : Dl;                                            \
    float E_[8];                                                               \
    E_[0] = fminf(D[0], bprev + cA[0].x);                                      \
    E_[1] = fminf(D[1], D[0] + cA[0].y);                                       \
    E_[2] = fminf(D[2], D[1] + cA[0].z);                                       \
    E_[3] = fminf(D[3], D[2] + cA[0].w);                                       \
    E_[4] = fminf(D[4], D[3] + cB[0].x);                                       \
    E_[5] = fminf(D[5], D[4] + cB[0].y);                                       \
    E_[6] = fminf(D[6], D[5] + cB[0].z);                                       \
    E_[7] = fminf(D[7], D[6] + cB[0].w);                                       \
    float t1_[8];                                                              \
    t1_[0] = E_[0];                                                            \
    _Pragma("unroll")                                                          \
    for (int k = 1; k < 8; ++k) t1_[k] = fminf(E_[k], E_[k-1]);                \
    float t2_[8];                                                              \
    t2_[0] = t1_[0]; t2_[1] = t1_[1];                                          \
    _Pragma("unroll")                                                          \
    for (int k = 2; k < 8; ++k) t2_[k] = fminf(t1_[k], t1_[k-2]);              \
    float t3_[8];                                                              \
    _Pragma("unroll")                                                          \
    for (int k = 0; k < 4; ++k) t3_[k] = t2_[k];                               \
    _Pragma("unroll")                                                          \
    for (int k = 4; k < 8; ++k) t3_[k] = fminf(t2_[k], t2_[k-4]);              \
    if (COMMIT) {                                                              \
        _Pragma("unroll")                                                      \
        for (int k = 0; k < 8; ++k) D[k] = fminf(t3_[k], Dl_eff);              \
    }                                                                          \
    float sh_ = __shfl_up_sync(0xffffffffu, D[7], 1);                          \
    bprev = Dl_eff;                                                            \
    Dl    = sh_;                                                               \
    cA[0] = cA[1]; cA[1] = cA[2]; cA[2] = cA[3]; cA[3] = nA_;                  \
    cB[0] = cB[1]; cB[1] = cB[2]; cB[2] = cB[3]; cB[3] = nB_;                  \
    xo0 = xo1; xo1 = xo2; xo2 = xo3; xo3 = xnew_;                              \
} while (0)

__global__ void __launch_bounds__(32, 4) dp_kernel(
    const int* __restrict__ xlen,
    const int* __restrict__ ylen,
    float* __restrict__ out)
{
    const int b    = blockIdx.x;
    const int lane = threadIdx.x;
    const int xl   = xlen[b] - 1;   // target row (1..511)
    const int yl   = ylen[b] - 1;   // target col (1..255)

    const char* Gtb = (const char*)(g_Gt + (size_t)b * S_DIM * LY) + lane * 32;
    const int*  xpb = g_xoff + b * XOFF_STRIDE;

    const int t_lane = (yl - 1) >> 3;
    const int k_t    = (yl - 1) & 7;
    const int s_end  = xl + t_lane;
    const bool is0   = (lane == 0);

    float D[8];
    #pragma unroll
    for (int k = 0; k < 8; ++k) D[k] = 0.0f;   // row 0: D'' = 0

    float Dl = 0.0f, bprev = 0.0f;

    // prefill cost pipeline: step sigma uses xoff idx sigma - lane + 31
    float4 cA[4], cB[4];
    #pragma unroll
    for (int p = 0; p < 4; ++p) {
        int xv = xpb[32 - lane + p];            // steps 1..4
        const char* r = Gtb + xv;
        cA[p] = *(const float4*)r;
        cB[p] = *(const float4*)(r + 16);
    }
    int xo0 = xpb[36 - lane];                   // step 5
    int xo1 = xpb[37 - lane];
    int xo2 = xpb[38 - lane];
    int xo3 = xpb[39 - lane];
    const int* xpr = xpb + 40 - lane;           // step 9 onward

    int s = 1;
    const int rampEnd = min(31, s_end);
    #pragma unroll 4
    for (; s <= rampEnd; ++s) {
        const bool act = (s > lane);
        DP_STEP(act);
    }
    #pragma unroll 4
    for (; s <= s_end; ++s) {
        DP_STEP(true);
    }

    if (lane == t_lane) out[b] = D[k_t] + (float)(xl + yl);
}

extern "C" void kernel_launch(void* const* d_in, const int* in_sizes, int n_in,
                              void* d_out, int out_size) {
    const float* P    = (const float*)d_in[0];
    const int*   xs   = (const int*)d_in[1];
    const int*   ys   = (const int*)d_in[2];
    const int*   xlen = (const int*)d_in[3];
    const int*   ylen = (const int*)d_in[4];
    float*       out  = (float*)d_out;

    softmax_neg_kernel<<<S_DIM, 32>>>(P);
    build_kernel<<<B_DIM, 256>>>(xs, ys, xlen);
    dp_kernel<<<B_DIM, 32>>>(xlen, ylen, out);
}